// round 1
// baseline (speedup 1.0000x reference)
#include <cuda_runtime.h>
#include <math_constants.h>

// Problem constants
#define BATCH 8
#define TSEQ  2048
#define CDIM  1024
#define HS    64
#define BT    (BATCH * TSEQ)   // 16384 rows

typedef unsigned long long u64;

// Scratch for projected Q, K, V (4 MB each) — __device__ globals per allocation rules.
__device__ float g_q[BT * HS];
__device__ float g_k[BT * HS];
__device__ float g_v[BT * HS];

// ---------------- packed fp32x2 helpers (Blackwell FFMA2 path) ----------------
__device__ __forceinline__ u64 pk2(float lo, float hi) {
    u64 r; asm("mov.b64 %0, {%1, %2};" : "=l"(r) : "f"(lo), "f"(hi)); return r;
}
__device__ __forceinline__ float2 upk2(u64 v) {
    float2 f; asm("mov.b64 {%0, %1}, %2;" : "=f"(f.x), "=f"(f.y) : "l"(v)); return f;
}
__device__ __forceinline__ void fma2(u64& d, u64 a, u64 b) {
    asm("fma.rn.f32x2 %0, %1, %2, %0;" : "+l"(d) : "l"(a), "l"(b));
}
__device__ __forceinline__ u64 mul2(u64 a, u64 b) {
    u64 r; asm("mul.rn.f32x2 %0, %1, %2;" : "=l"(r) : "l"(a), "l"(b)); return r;
}

// =============================================================================
// Projection kernel: Y[M=16384, 64] = X[M, 1024] @ W[1024, 64]
// blockIdx.y selects {Q, K, V}. 64-row tile per block, 256 threads, 4x4 micro.
// Accumulators are packed over k-parity: acc = (sum over even k, sum over odd k).
// =============================================================================
#define PKB 32          // K-chunk
#define PST 34          // smem row stride (floats): 34*4B = 136B, 8B aligned, bank-safe

__global__ __launch_bounds__(256, 2)
void proj_kernel(const float* __restrict__ xq, const float* __restrict__ xkv,
                 const float* __restrict__ Wq, const float* __restrict__ Wk,
                 const float* __restrict__ Wv)
{
    __shared__ float Xs[64 * PST];   // Xs[r][k]
    __shared__ float Wt[64 * PST];   // Wt[h][k]  (W transposed)

    const float* X; const float* W; float* Y;
    if (blockIdx.y == 0)      { X = xq;  W = Wq; Y = g_q; }
    else if (blockIdx.y == 1) { X = xkv; W = Wk; Y = g_k; }
    else                      { X = xkv; W = Wv; Y = g_v; }

    const int tid = threadIdx.x;
    const int tx  = tid & 15;        // col group
    const int ty  = tid >> 4;        // row group
    const int row0 = blockIdx.x * 64;
    const float* Xp = X + (size_t)row0 * CDIM;

    u64 acc[4][4];
#pragma unroll
    for (int i = 0; i < 4; i++)
#pragma unroll
        for (int j = 0; j < 4; j++) acc[i][j] = 0ull;

    float4 xr[2], wr[2];
    // prefetch chunk 0
#pragma unroll
    for (int i = 0; i < 2; i++) {
        int idx = tid + 256 * i;
        int r = idx >> 3, k4 = idx & 7;                 // X tile: 64 x 32 = 512 float4
        xr[i] = *(const float4*)(Xp + r * CDIM + k4 * 4);
        int kk = idx >> 4, h4 = idx & 15;               // W tile: 32 x 64 = 512 float4
        wr[i] = *(const float4*)(W + kk * HS + h4 * 4);
    }

    for (int ch = 0; ch < CDIM / PKB; ch++) {
        __syncthreads();
        // commit prefetched regs to smem
#pragma unroll
        for (int i = 0; i < 2; i++) {
            int idx = tid + 256 * i;
            int r = idx >> 3, k4 = idx & 7;
            float* p = &Xs[r * PST + k4 * 4];
            p[0] = xr[i].x; p[1] = xr[i].y; p[2] = xr[i].z; p[3] = xr[i].w;
            int kk = idx >> 4, h4 = idx & 15;
            Wt[(h4 * 4 + 0) * PST + kk] = wr[i].x;
            Wt[(h4 * 4 + 1) * PST + kk] = wr[i].y;
            Wt[(h4 * 4 + 2) * PST + kk] = wr[i].z;
            Wt[(h4 * 4 + 3) * PST + kk] = wr[i].w;
        }
        __syncthreads();
        // prefetch next chunk
        if (ch + 1 < CDIM / PKB) {
            int k0 = (ch + 1) * PKB;
#pragma unroll
            for (int i = 0; i < 2; i++) {
                int idx = tid + 256 * i;
                int r = idx >> 3, k4 = idx & 7;
                xr[i] = *(const float4*)(Xp + r * CDIM + k0 + k4 * 4);
                int kk = idx >> 4, h4 = idx & 15;
                wr[i] = *(const float4*)(W + (k0 + kk) * HS + h4 * 4);
            }
        }
        // compute: 16 k-pairs x 16 FFMA2
#pragma unroll
        for (int k = 0; k < PKB; k += 2) {
            u64 a2[4], b2[4];
#pragma unroll
            for (int i = 0; i < 4; i++) a2[i] = *(const u64*)&Xs[(ty * 4 + i) * PST + k];
#pragma unroll
            for (int j = 0; j < 4; j++) b2[j] = *(const u64*)&Wt[(tx + 16 * j) * PST + k];
#pragma unroll
            for (int i = 0; i < 4; i++)
#pragma unroll
                for (int j = 0; j < 4; j++) fma2(acc[i][j], a2[i], b2[j]);
        }
    }

#pragma unroll
    for (int i = 0; i < 4; i++) {
        int r = row0 + ty * 4 + i;
#pragma unroll
        for (int j = 0; j < 4; j++) {
            float2 f = upk2(acc[i][j]);
            Y[r * HS + tx + 16 * j] = f.x + f.y;
        }
    }
}

// =============================================================================
// Flash attention kernel: per (batch b, 64-query tile qt).
// S = (Q Kt) * C^-0.5, causal, online softmax, O += P V. All GEMMs in FFMA2.
// Column mapping c_j / h_j = tx + 16*j -> conflict-free LDS.64 (stride 66).
// =============================================================================
#define AST 66   // smem row stride (floats): 66*4 = 264B, 8B aligned; 66 mod 32 == 2

__global__ __launch_bounds__(256, 2)
void attn_kernel(float* __restrict__ out)
{
    extern __shared__ float sm[];
    float* Qs = sm;                 // [64][AST]  Q[r][d]
    float* Ks = Qs + 64 * AST;      // [64][AST]  K[c][d]
    float* Vt = Ks + 64 * AST;      // [64][AST]  V^T[h][c]
    float* Ps = Vt + 64 * AST;      // [64][AST]  P[r][c]

    const int tid = threadIdx.x;
    const int tx  = tid & 15;
    const int ty  = tid >> 4;
    const int qt  = blockIdx.x;
    const int b   = blockIdx.y;
    const int q0  = qt * 64;

    const float* Qg = g_q + (size_t)b * TSEQ * HS;
    const float* Kg = g_k + (size_t)b * TSEQ * HS;
    const float* Vg = g_v + (size_t)b * TSEQ * HS;

    // load Q tile (64 x 64 floats = 1024 float4)
#pragma unroll
    for (int i = 0; i < 4; i++) {
        int idx = tid + 256 * i;
        int r = idx >> 4, d4 = idx & 15;
        float4 v = *(const float4*)(Qg + (q0 + r) * HS + d4 * 4);
        float* p = &Qs[r * AST + d4 * 4];
        p[0] = v.x; p[1] = v.y; p[2] = v.z; p[3] = v.w;
    }

    u64 o2[4][4];
#pragma unroll
    for (int i = 0; i < 4; i++)
#pragma unroll
        for (int j = 0; j < 4; j++) o2[i][j] = 0ull;
    float m[4], l[4];
#pragma unroll
    for (int i = 0; i < 4; i++) { m[i] = -CUDART_INF_F; l[i] = 0.f; }

    for (int kt = 0; kt <= qt; kt++) {
        const int k0 = kt * 64;
        __syncthreads();   // previous GEMM2 must finish before overwriting Ks/Vt
        // load K tile [c][d] and V transposed [h][c]
#pragma unroll
        for (int i = 0; i < 4; i++) {
            int idx = tid + 256 * i;
            int c = idx >> 4, d4 = idx & 15;
            float4 kv = *(const float4*)(Kg + (k0 + c) * HS + d4 * 4);
            float* p = &Ks[c * AST + d4 * 4];
            p[0] = kv.x; p[1] = kv.y; p[2] = kv.z; p[3] = kv.w;
            float4 vv = *(const float4*)(Vg + (k0 + c) * HS + d4 * 4);
            Vt[(d4 * 4 + 0) * AST + c] = vv.x;
            Vt[(d4 * 4 + 1) * AST + c] = vv.y;
            Vt[(d4 * 4 + 2) * AST + c] = vv.z;
            Vt[(d4 * 4 + 3) * AST + c] = vv.w;
        }
        __syncthreads();

        // ---- GEMM1: S = Q K^T (packed over d-parity) ----
        u64 s2[4][4];
#pragma unroll
        for (int i = 0; i < 4; i++)
#pragma unroll
            for (int j = 0; j < 4; j++) s2[i][j] = 0ull;
#pragma unroll 8
        for (int d = 0; d < HS; d += 2) {
            u64 a2[4], b2[4];
#pragma unroll
            for (int i = 0; i < 4; i++) a2[i] = *(const u64*)&Qs[(ty * 4 + i) * AST + d];
#pragma unroll
            for (int j = 0; j < 4; j++) b2[j] = *(const u64*)&Ks[(tx + 16 * j) * AST + d];
#pragma unroll
            for (int i = 0; i < 4; i++)
#pragma unroll
                for (int j = 0; j < 4; j++) fma2(s2[i][j], a2[i], b2[j]);
        }

        // ---- scale + causal mask + online softmax ----
        float sv[4][4];
#pragma unroll
        for (int i = 0; i < 4; i++)
#pragma unroll
            for (int j = 0; j < 4; j++) {
                float2 f = upk2(s2[i][j]);
                sv[i][j] = (f.x + f.y) * 0.03125f;   // C^-0.5 = 1024^-0.5
            }
        if (kt == qt) {
#pragma unroll
            for (int i = 0; i < 4; i++)
#pragma unroll
                for (int j = 0; j < 4; j++)
                    if (k0 + tx + 16 * j > q0 + ty * 4 + i) sv[i][j] = -CUDART_INF_F;
        }
#pragma unroll
        for (int i = 0; i < 4; i++) {
            float rm = fmaxf(fmaxf(sv[i][0], sv[i][1]), fmaxf(sv[i][2], sv[i][3]));
            rm = fmaxf(rm, __shfl_xor_sync(0xffffffffu, rm, 8));
            rm = fmaxf(rm, __shfl_xor_sync(0xffffffffu, rm, 4));
            rm = fmaxf(rm, __shfl_xor_sync(0xffffffffu, rm, 2));
            rm = fmaxf(rm, __shfl_xor_sync(0xffffffffu, rm, 1));
            float mn = fmaxf(m[i], rm);
            float sc = __expf(m[i] - mn);            // first tile: exp(-inf)=0
            m[i] = mn;
            float rs = 0.f;
#pragma unroll
            for (int j = 0; j < 4; j++) {
                float p = __expf(sv[i][j] - mn);
                rs += p;
                Ps[(ty * 4 + i) * AST + tx + 16 * j] = p;
            }
            rs += __shfl_xor_sync(0xffffffffu, rs, 8);
            rs += __shfl_xor_sync(0xffffffffu, rs, 4);
            rs += __shfl_xor_sync(0xffffffffu, rs, 2);
            rs += __shfl_xor_sync(0xffffffffu, rs, 1);
            l[i] = l[i] * sc + rs;
            u64 sc2 = pk2(sc, sc);
#pragma unroll
            for (int j = 0; j < 4; j++) o2[i][j] = mul2(o2[i][j], sc2);
        }
        __syncthreads();   // Ps complete before GEMM2 reads

        // ---- GEMM2: O += P V (packed over c-parity) ----
#pragma unroll 8
        for (int c = 0; c < 64; c += 2) {
            u64 a2[4], b2[4];
#pragma unroll
            for (int i = 0; i < 4; i++) a2[i] = *(const u64*)&Ps[(ty * 4 + i) * AST + c];
#pragma unroll
            for (int j = 0; j < 4; j++) b2[j] = *(const u64*)&Vt[(tx + 16 * j) * AST + c];
#pragma unroll
            for (int i = 0; i < 4; i++)
#pragma unroll
                for (int j = 0; j < 4; j++) fma2(o2[i][j], a2[i], b2[j]);
        }
    }

    // epilogue: O / l
    float* Og = out + ((size_t)b * TSEQ + q0) * HS;
#pragma unroll
    for (int i = 0; i < 4; i++) {
        float inv = 1.f / l[i];
#pragma unroll
        for (int j = 0; j < 4; j++) {
            float2 f = upk2(o2[i][j]);
            Og[(ty * 4 + i) * HS + tx + 16 * j] = (f.x + f.y) * inv;
        }
    }
}

// =============================================================================
extern "C" void kernel_launch(void* const* d_in, const int* in_sizes, int n_in,
                              void* d_out, int out_size)
{
    const float* xq  = (const float*)d_in[0];
    const float* xkv = (const float*)d_in[1];
    const float* Wq  = (const float*)d_in[2];
    const float* Wk  = (const float*)d_in[3];
    const float* Wv  = (const float*)d_in[4];
    float* out = (float*)d_out;

    // idempotent, not a stream op — safe under graph capture
    cudaFuncSetAttribute(attn_kernel, cudaFuncAttributeMaxDynamicSharedMemorySize,
                         4 * 64 * AST * 4);

    proj_kernel<<<dim3(BT / 64, 3), 256>>>(xq, xkv, Wq, Wk, Wv);

    attn_kernel<<<dim3(TSEQ / 64, BATCH), 256, 4 * 64 * AST * 4>>>(out);
}

// round 2
// speedup vs baseline: 1.0001x; 1.0001x over previous
#include <cuda_runtime.h>
#include <math_constants.h>

// Problem constants
#define BATCH 8
#define TSEQ  2048
#define CDIM  1024
#define HS    64
#define BT    (BATCH * TSEQ)   // 16384 rows

typedef unsigned long long u64;

// Scratch for projected Q, K, V (4 MB each) — __device__ globals per allocation rules.
__device__ float g_q[BT * HS];
__device__ float g_k[BT * HS];
__device__ float g_v[BT * HS];

// ---------------- packed fp32x2 helpers (Blackwell FFMA2 path) ----------------
__device__ __forceinline__ u64 pk2(float lo, float hi) {
    u64 r; asm("mov.b64 %0, {%1, %2};" : "=l"(r) : "f"(lo), "f"(hi)); return r;
}
__device__ __forceinline__ float2 upk2(u64 v) {
    float2 f; asm("mov.b64 {%0, %1}, %2;" : "=f"(f.x), "=f"(f.y) : "l"(v)); return f;
}
__device__ __forceinline__ void fma2(u64& d, u64 a, u64 b) {
    asm("fma.rn.f32x2 %0, %1, %2, %0;" : "+l"(d) : "l"(a), "l"(b));
}
__device__ __forceinline__ u64 mul2(u64 a, u64 b) {
    u64 r; asm("mul.rn.f32x2 %0, %1, %2;" : "=l"(r) : "l"(a), "l"(b)); return r;
}

// =============================================================================
// Projection kernel: Y[M=16384, 64] = X[M, 1024] @ W[1024, 64]
// blockIdx.y selects {Q, K, V}. 64-row tile per block, 256 threads, 4x4 micro.
// Accumulators are packed over k-parity: acc = (sum over even k, sum over odd k).
// =============================================================================
#define PKB 32          // K-chunk
#define PST 34          // smem row stride (floats): 34*4B = 136B, 8B aligned, bank-safe

__global__ __launch_bounds__(256, 2)
void proj_kernel(const float* __restrict__ xq, const float* __restrict__ xkv,
                 const float* __restrict__ Wq, const float* __restrict__ Wk,
                 const float* __restrict__ Wv)
{
    __shared__ float Xs[64 * PST];   // Xs[r][k]
    __shared__ float Wt[64 * PST];   // Wt[h][k]  (W transposed)

    const float* X; const float* W; float* Y;
    if (blockIdx.y == 0)      { X = xq;  W = Wq; Y = g_q; }
    else if (blockIdx.y == 1) { X = xkv; W = Wk; Y = g_k; }
    else                      { X = xkv; W = Wv; Y = g_v; }

    const int tid = threadIdx.x;
    const int tx  = tid & 15;        // col group
    const int ty  = tid >> 4;        // row group
    const int row0 = blockIdx.x * 64;
    const float* Xp = X + (size_t)row0 * CDIM;

    u64 acc[4][4];
#pragma unroll
    for (int i = 0; i < 4; i++)
#pragma unroll
        for (int j = 0; j < 4; j++) acc[i][j] = 0ull;

    float4 xr[2], wr[2];
    // prefetch chunk 0
#pragma unroll
    for (int i = 0; i < 2; i++) {
        int idx = tid + 256 * i;
        int r = idx >> 3, k4 = idx & 7;                 // X tile: 64 x 32 = 512 float4
        xr[i] = *(const float4*)(Xp + r * CDIM + k4 * 4);
        int kk = idx >> 4, h4 = idx & 15;               // W tile: 32 x 64 = 512 float4
        wr[i] = *(const float4*)(W + kk * HS + h4 * 4);
    }

    for (int ch = 0; ch < CDIM / PKB; ch++) {
        __syncthreads();
        // commit prefetched regs to smem
#pragma unroll
        for (int i = 0; i < 2; i++) {
            int idx = tid + 256 * i;
            int r = idx >> 3, k4 = idx & 7;
            float* p = &Xs[r * PST + k4 * 4];
            p[0] = xr[i].x; p[1] = xr[i].y; p[2] = xr[i].z; p[3] = xr[i].w;
            int kk = idx >> 4, h4 = idx & 15;
            Wt[(h4 * 4 + 0) * PST + kk] = wr[i].x;
            Wt[(h4 * 4 + 1) * PST + kk] = wr[i].y;
            Wt[(h4 * 4 + 2) * PST + kk] = wr[i].z;
            Wt[(h4 * 4 + 3) * PST + kk] = wr[i].w;
        }
        __syncthreads();
        // prefetch next chunk
        if (ch + 1 < CDIM / PKB) {
            int k0 = (ch + 1) * PKB;
#pragma unroll
            for (int i = 0; i < 2; i++) {
                int idx = tid + 256 * i;
                int r = idx >> 3, k4 = idx & 7;
                xr[i] = *(const float4*)(Xp + r * CDIM + k0 + k4 * 4);
                int kk = idx >> 4, h4 = idx & 15;
                wr[i] = *(const float4*)(W + (k0 + kk) * HS + h4 * 4);
            }
        }
        // compute: 16 k-pairs x 16 FFMA2
#pragma unroll
        for (int k = 0; k < PKB; k += 2) {
            u64 a2[4], b2[4];
#pragma unroll
            for (int i = 0; i < 4; i++) a2[i] = *(const u64*)&Xs[(ty * 4 + i) * PST + k];
#pragma unroll
            for (int j = 0; j < 4; j++) b2[j] = *(const u64*)&Wt[(tx + 16 * j) * PST + k];
#pragma unroll
            for (int i = 0; i < 4; i++)
#pragma unroll
                for (int j = 0; j < 4; j++) fma2(acc[i][j], a2[i], b2[j]);
        }
    }

#pragma unroll
    for (int i = 0; i < 4; i++) {
        int r = row0 + ty * 4 + i;
#pragma unroll
        for (int j = 0; j < 4; j++) {
            float2 f = upk2(acc[i][j]);
            Y[r * HS + tx + 16 * j] = f.x + f.y;
        }
    }
}

// =============================================================================
// Flash attention kernel: per (batch b, 64-query tile qt).
// S = (Q Kt) * C^-0.5, causal, online softmax, O += P V. All GEMMs in FFMA2.
// Column mapping c_j / h_j = tx + 16*j -> conflict-free LDS.64 (stride 66).
// =============================================================================
#define AST 66   // smem row stride (floats): 66*4 = 264B, 8B aligned; 66 mod 32 == 2

__global__ __launch_bounds__(256, 2)
void attn_kernel(float* __restrict__ out)
{
    extern __shared__ float sm[];
    float* Qs = sm;                 // [64][AST]  Q[r][d]
    float* Ks = Qs + 64 * AST;      // [64][AST]  K[c][d]
    float* Vt = Ks + 64 * AST;      // [64][AST]  V^T[h][c]
    float* Ps = Vt + 64 * AST;      // [64][AST]  P[r][c]

    const int tid = threadIdx.x;
    const int tx  = tid & 15;
    const int ty  = tid >> 4;
    const int qt  = blockIdx.x;
    const int b   = blockIdx.y;
    const int q0  = qt * 64;

    const float* Qg = g_q + (size_t)b * TSEQ * HS;
    const float* Kg = g_k + (size_t)b * TSEQ * HS;
    const float* Vg = g_v + (size_t)b * TSEQ * HS;

    // load Q tile (64 x 64 floats = 1024 float4)
#pragma unroll
    for (int i = 0; i < 4; i++) {
        int idx = tid + 256 * i;
        int r = idx >> 4, d4 = idx & 15;
        float4 v = *(const float4*)(Qg + (q0 + r) * HS + d4 * 4);
        float* p = &Qs[r * AST + d4 * 4];
        p[0] = v.x; p[1] = v.y; p[2] = v.z; p[3] = v.w;
    }

    u64 o2[4][4];
#pragma unroll
    for (int i = 0; i < 4; i++)
#pragma unroll
        for (int j = 0; j < 4; j++) o2[i][j] = 0ull;
    float m[4], l[4];
#pragma unroll
    for (int i = 0; i < 4; i++) { m[i] = -CUDART_INF_F; l[i] = 0.f; }

    for (int kt = 0; kt <= qt; kt++) {
        const int k0 = kt * 64;
        __syncthreads();   // previous GEMM2 must finish before overwriting Ks/Vt
        // load K tile [c][d] and V transposed [h][c]
#pragma unroll
        for (int i = 0; i < 4; i++) {
            int idx = tid + 256 * i;
            int c = idx >> 4, d4 = idx & 15;
            float4 kv = *(const float4*)(Kg + (k0 + c) * HS + d4 * 4);
            float* p = &Ks[c * AST + d4 * 4];
            p[0] = kv.x; p[1] = kv.y; p[2] = kv.z; p[3] = kv.w;
            float4 vv = *(const float4*)(Vg + (k0 + c) * HS + d4 * 4);
            Vt[(d4 * 4 + 0) * AST + c] = vv.x;
            Vt[(d4 * 4 + 1) * AST + c] = vv.y;
            Vt[(d4 * 4 + 2) * AST + c] = vv.z;
            Vt[(d4 * 4 + 3) * AST + c] = vv.w;
        }
        __syncthreads();

        // ---- GEMM1: S = Q K^T (packed over d-parity) ----
        u64 s2[4][4];
#pragma unroll
        for (int i = 0; i < 4; i++)
#pragma unroll
            for (int j = 0; j < 4; j++) s2[i][j] = 0ull;
#pragma unroll 8
        for (int d = 0; d < HS; d += 2) {
            u64 a2[4], b2[4];
#pragma unroll
            for (int i = 0; i < 4; i++) a2[i] = *(const u64*)&Qs[(ty * 4 + i) * AST + d];
#pragma unroll
            for (int j = 0; j < 4; j++) b2[j] = *(const u64*)&Ks[(tx + 16 * j) * AST + d];
#pragma unroll
            for (int i = 0; i < 4; i++)
#pragma unroll
                for (int j = 0; j < 4; j++) fma2(s2[i][j], a2[i], b2[j]);
        }

        // ---- scale + causal mask + online softmax ----
        float sv[4][4];
#pragma unroll
        for (int i = 0; i < 4; i++)
#pragma unroll
            for (int j = 0; j < 4; j++) {
                float2 f = upk2(s2[i][j]);
                sv[i][j] = (f.x + f.y) * 0.03125f;   // C^-0.5 = 1024^-0.5
            }
        if (kt == qt) {
#pragma unroll
            for (int i = 0; i < 4; i++)
#pragma unroll
                for (int j = 0; j < 4; j++)
                    if (k0 + tx + 16 * j > q0 + ty * 4 + i) sv[i][j] = -CUDART_INF_F;
        }
#pragma unroll
        for (int i = 0; i < 4; i++) {
            float rm = fmaxf(fmaxf(sv[i][0], sv[i][1]), fmaxf(sv[i][2], sv[i][3]));
            rm = fmaxf(rm, __shfl_xor_sync(0xffffffffu, rm, 8));
            rm = fmaxf(rm, __shfl_xor_sync(0xffffffffu, rm, 4));
            rm = fmaxf(rm, __shfl_xor_sync(0xffffffffu, rm, 2));
            rm = fmaxf(rm, __shfl_xor_sync(0xffffffffu, rm, 1));
            float mn = fmaxf(m[i], rm);
            float sc = __expf(m[i] - mn);            // first tile: exp(-inf)=0
            m[i] = mn;
            float rs = 0.f;
#pragma unroll
            for (int j = 0; j < 4; j++) {
                float p = __expf(sv[i][j] - mn);
                rs += p;
                Ps[(ty * 4 + i) * AST + tx + 16 * j] = p;
            }
            rs += __shfl_xor_sync(0xffffffffu, rs, 8);
            rs += __shfl_xor_sync(0xffffffffu, rs, 4);
            rs += __shfl_xor_sync(0xffffffffu, rs, 2);
            rs += __shfl_xor_sync(0xffffffffu, rs, 1);
            l[i] = l[i] * sc + rs;
            u64 sc2 = pk2(sc, sc);
#pragma unroll
            for (int j = 0; j < 4; j++) o2[i][j] = mul2(o2[i][j], sc2);
        }
        __syncthreads();   // Ps complete before GEMM2 reads

        // ---- GEMM2: O += P V (packed over c-parity) ----
#pragma unroll 8
        for (int c = 0; c < 64; c += 2) {
            u64 a2[4], b2[4];
#pragma unroll
            for (int i = 0; i < 4; i++) a2[i] = *(const u64*)&Ps[(ty * 4 + i) * AST + c];
#pragma unroll
            for (int j = 0; j < 4; j++) b2[j] = *(const u64*)&Vt[(tx + 16 * j) * AST + c];
#pragma unroll
            for (int i = 0; i < 4; i++)
#pragma unroll
                for (int j = 0; j < 4; j++) fma2(o2[i][j], a2[i], b2[j]);
        }
    }

    // epilogue: O / l
    float* Og = out + ((size_t)b * TSEQ + q0) * HS;
#pragma unroll
    for (int i = 0; i < 4; i++) {
        float inv = 1.f / l[i];
#pragma unroll
        for (int j = 0; j < 4; j++) {
            float2 f = upk2(o2[i][j]);
            Og[(ty * 4 + i) * HS + tx + 16 * j] = (f.x + f.y) * inv;
        }
    }
}

// =============================================================================
extern "C" void kernel_launch(void* const* d_in, const int* in_sizes, int n_in,
                              void* d_out, int out_size)
{
    const float* xq  = (const float*)d_in[0];
    const float* xkv = (const float*)d_in[1];
    const float* Wq  = (const float*)d_in[2];
    const float* Wk  = (const float*)d_in[3];
    const float* Wv  = (const float*)d_in[4];
    float* out = (float*)d_out;

    // idempotent, not a stream op — safe under graph capture
    cudaFuncSetAttribute(attn_kernel, cudaFuncAttributeMaxDynamicSharedMemorySize,
                         4 * 64 * AST * 4);

    proj_kernel<<<dim3(BT / 64, 3), 256>>>(xq, xkv, Wq, Wk, Wv);

    attn_kernel<<<dim3(TSEQ / 64, BATCH), 256, 4 * 64 * AST * 4>>>(out);
}

// round 4
// speedup vs baseline: 2.0570x; 2.0567x over previous
#include <cuda_runtime.h>
#include <cuda_bf16.h>
#include <math_constants.h>

typedef unsigned int u32;
typedef __nv_bfloat16 bf;

// Problem constants
#define BATCH 8
#define TSEQ  2048
#define CDIM  1024
#define HS    64
#define BT    (BATCH * TSEQ)   // 16384

// Scratch for projected Q, K, V — __device__ globals per allocation rules.
__device__ float g_q[BT * HS];
__device__ float g_k[BT * HS];
__device__ float g_v[BT * HS];

// ---------------- bf16 mma.sync (legacy HMMA path — baseline PTX, works on sm_103) ----
__device__ __forceinline__ void mma16816(float* d, const u32* a, const u32* b) {
    asm volatile(
        "mma.sync.aligned.m16n8k16.row.col.f32.bf16.bf16.f32 "
        "{%0,%1,%2,%3}, {%4,%5,%6,%7}, {%8,%9}, {%0,%1,%2,%3};"
        : "+f"(d[0]), "+f"(d[1]), "+f"(d[2]), "+f"(d[3])
        : "r"(a[0]), "r"(a[1]), "r"(a[2]), "r"(a[3]), "r"(b[0]), "r"(b[1]));
}

// Split two fp32 into packed-bf16 hi and lo words (x = hi + lo to ~16 mantissa bits)
__device__ __forceinline__ void split2(float x0, float x1, u32& hi, u32& lo) {
    __nv_bfloat162 h = __floats2bfloat162_rn(x0, x1);
    float r0 = x0 - __bfloat162float(h.x);
    float r1 = x1 - __bfloat162float(h.y);
    __nv_bfloat162 lw = __floats2bfloat162_rn(r0, r1);
    hi = *(u32*)&h;
    lo = *(u32*)&lw;
}

// smem row stride for all bf16 tiles: 64 data + 8 pad = 72 bf16 (144B)
// frag-load banks: (row*36 + pair) mod 32 = (row*4 + pair) mod 32 -> conflict-free
#define ST 72

// =============================================================================
// Projection: Y[16384,64] = X[16384,1024] @ W[1024,64], blockIdx.y -> {Q,K,V}
// CTA: 256 threads (8 warps), tile 256(M) x 64(N), K chunked by 64.
// Warp: 32 rows (2 x m16), all 8 n8 tiles. 3-pass split-bf16.
// =============================================================================
#define P_AHI 0
#define P_ALO (256 * ST * 2)                  // 36864
#define P_BHI (2 * 256 * ST * 2)              // 73728
#define P_BLO (P_BHI + 64 * ST * 2)           // 82944
#define P_SMEM (P_BHI + 2 * 64 * ST * 2)      // 92160

__global__ __launch_bounds__(256, 2)
void proj_kernel(const float* __restrict__ xq, const float* __restrict__ xkv,
                 const float* __restrict__ Wq, const float* __restrict__ Wk,
                 const float* __restrict__ Wv)
{
    extern __shared__ char dsm[];
    bf* Ahi = (bf*)(dsm + P_AHI); bf* Alo = (bf*)(dsm + P_ALO);
    bf* Bhi = (bf*)(dsm + P_BHI); bf* Blo = (bf*)(dsm + P_BLO);

    const int tid = threadIdx.x, wid = tid >> 5, l = tid & 31;
    const int g = l >> 2, pp = l & 3;

    const float* X; const float* W; float* Y;
    if (blockIdx.y == 0)      { X = xq;  W = Wq; Y = g_q; }
    else if (blockIdx.y == 1) { X = xkv; W = Wk; Y = g_k; }
    else                      { X = xkv; W = Wv; Y = g_v; }

    const int m0 = blockIdx.x * 256;
    const float* Xp = X + (size_t)m0 * CDIM;

    float acc[2][8][4];
#pragma unroll
    for (int m = 0; m < 2; m++)
#pragma unroll
        for (int t = 0; t < 8; t++)
#pragma unroll
            for (int i = 0; i < 4; i++) acc[m][t][i] = 0.f;

    for (int ch = 0; ch < CDIM / 64; ch++) {
        const int k0 = ch * 64;
        __syncthreads();
        // A tile: 256 x 64 fp32 -> split -> smem (16 float4 / thread)
#pragma unroll 4
        for (int i = 0; i < 16; i++) {
            int idx = tid + 256 * i;
            int r = idx >> 4, k4 = idx & 15;
            float4 v = *(const float4*)(Xp + (size_t)r * CDIM + k0 + k4 * 4);
            u32 h0, l0, h1, l1;
            split2(v.x, v.y, h0, l0); split2(v.z, v.w, h1, l1);
            *(u32*)(Ahi + r * ST + k4 * 4)     = h0;
            *(u32*)(Ahi + r * ST + k4 * 4 + 2) = h1;
            *(u32*)(Alo + r * ST + k4 * 4)     = l0;
            *(u32*)(Alo + r * ST + k4 * 4 + 2) = l1;
        }
        // B tile: W[k][n] -> transposed [n][k] (4 float4 / thread)
#pragma unroll
        for (int i = 0; i < 4; i++) {
            int idx = tid + 256 * i;
            int kk = idx >> 4, n4 = idx & 15;
            float4 v = *(const float4*)(W + (size_t)(k0 + kk) * HS + n4 * 4);
            float vv[4] = {v.x, v.y, v.z, v.w};
#pragma unroll
            for (int e = 0; e < 4; e++) {
                bf h = __float2bfloat16(vv[e]);
                Bhi[(n4 * 4 + e) * ST + kk] = h;
                Blo[(n4 * 4 + e) * ST + kk] = __float2bfloat16(vv[e] - __bfloat162float(h));
            }
        }
        __syncthreads();

#pragma unroll
        for (int k16 = 0; k16 < 4; k16++) {
            u32 ah[2][4], al[2][4];
#pragma unroll
            for (int m = 0; m < 2; m++) {
                const bf* ba = Ahi + (wid * 32 + m * 16 + g) * ST + k16 * 16 + pp * 2;
                ah[m][0] = *(const u32*)ba;
                ah[m][1] = *(const u32*)(ba + 8 * ST);
                ah[m][2] = *(const u32*)(ba + 8);
                ah[m][3] = *(const u32*)(ba + 8 * ST + 8);
                const bf* bl_ = Alo + (wid * 32 + m * 16 + g) * ST + k16 * 16 + pp * 2;
                al[m][0] = *(const u32*)bl_;
                al[m][1] = *(const u32*)(bl_ + 8 * ST);
                al[m][2] = *(const u32*)(bl_ + 8);
                al[m][3] = *(const u32*)(bl_ + 8 * ST + 8);
            }
#pragma unroll
            for (int t = 0; t < 8; t++) {
                const bf* bb = Bhi + (t * 8 + g) * ST + k16 * 16 + pp * 2;
                u32 bh[2] = {*(const u32*)bb, *(const u32*)(bb + 8)};
                const bf* bb2 = Blo + (t * 8 + g) * ST + k16 * 16 + pp * 2;
                u32 bl2[2] = {*(const u32*)bb2, *(const u32*)(bb2 + 8)};
#pragma unroll
                for (int m = 0; m < 2; m++) {
                    mma16816(acc[m][t], ah[m], bh);
                    mma16816(acc[m][t], al[m], bh);
                    mma16816(acc[m][t], ah[m], bl2);
                }
            }
        }
    }

    // epilogue: fp32 writes
#pragma unroll
    for (int m = 0; m < 2; m++)
#pragma unroll
        for (int t = 0; t < 8; t++) {
            int row = m0 + wid * 32 + m * 16 + g;
            int col = t * 8 + pp * 2;
            *(float2*)(Y + (size_t)row * HS + col)       = make_float2(acc[m][t][0], acc[m][t][1]);
            *(float2*)(Y + (size_t)(row + 8) * HS + col) = make_float2(acc[m][t][2], acc[m][t][3]);
        }
}

// =============================================================================
// Flash attention: CTA = (pair id, batch). Processes q-tiles qt and 31-qt
// sequentially (uniform 33 k-iterations per CTA). 128 threads (4 warps),
// warp owns 16 q-rows. 64x64 S tiles, split-bf16 3-pass MMA for both GEMMs.
// =============================================================================
#define A_QHI 0
#define A_QLO 9216
#define A_KHI 18432
#define A_KLO 27648
#define A_VHI 36864
#define A_VLO 46080
#define A_PHI 55296
#define A_PLO 64512
#define A_SMEM 73728

__global__ __launch_bounds__(128, 1)
void attn_kernel(float* __restrict__ out)
{
    extern __shared__ char dsm[];
    bf* Qhi = (bf*)(dsm + A_QHI); bf* Qlo = (bf*)(dsm + A_QLO);
    bf* Khi = (bf*)(dsm + A_KHI); bf* Klo = (bf*)(dsm + A_KLO);
    bf* Vhi = (bf*)(dsm + A_VHI); bf* Vlo = (bf*)(dsm + A_VLO);
    bf* Phi = (bf*)(dsm + A_PHI); bf* Plo = (bf*)(dsm + A_PLO);

    const int tid = threadIdx.x, wid = tid >> 5, l = tid & 31;
    const int g = l >> 2, pp = l & 3;
    const int b = blockIdx.y;

    const float* Qg = g_q + (size_t)b * TSEQ * HS;
    const float* Kg = g_k + (size_t)b * TSEQ * HS;
    const float* Vg = g_v + (size_t)b * TSEQ * HS;

    for (int rep = 0; rep < 2; rep++) {
        const int qt = rep ? (31 - (int)blockIdx.x) : (int)blockIdx.x;
        const int q0 = qt * 64;

        __syncthreads();   // smem reuse across reps / before Q overwrite
        // load + split Q tile (8 float4 / thread)
#pragma unroll
        for (int i = 0; i < 8; i++) {
            int idx = tid + 128 * i;
            int r = idx >> 4, d4 = idx & 15;
            float4 v = *(const float4*)(Qg + (size_t)(q0 + r) * HS + d4 * 4);
            u32 h0, l0, h1, l1;
            split2(v.x, v.y, h0, l0); split2(v.z, v.w, h1, l1);
            *(u32*)(Qhi + r * ST + d4 * 4)     = h0;
            *(u32*)(Qhi + r * ST + d4 * 4 + 2) = h1;
            *(u32*)(Qlo + r * ST + d4 * 4)     = l0;
            *(u32*)(Qlo + r * ST + d4 * 4 + 2) = l1;
        }
        __syncthreads();

        // hoist Q fragments into registers (reused every k-iteration)
        u32 qh[4][4], ql[4][4];
#pragma unroll
        for (int k16 = 0; k16 < 4; k16++) {
            const bf* ba = Qhi + (wid * 16 + g) * ST + k16 * 16 + pp * 2;
            qh[k16][0] = *(const u32*)ba;
            qh[k16][1] = *(const u32*)(ba + 8 * ST);
            qh[k16][2] = *(const u32*)(ba + 8);
            qh[k16][3] = *(const u32*)(ba + 8 * ST + 8);
            const bf* bb = Qlo + (wid * 16 + g) * ST + k16 * 16 + pp * 2;
            ql[k16][0] = *(const u32*)bb;
            ql[k16][1] = *(const u32*)(bb + 8 * ST);
            ql[k16][2] = *(const u32*)(bb + 8);
            ql[k16][3] = *(const u32*)(bb + 8 * ST + 8);
        }

        float o[8][4];
#pragma unroll
        for (int t = 0; t < 8; t++)
#pragma unroll
            for (int i = 0; i < 4; i++) o[t][i] = 0.f;
        float mrow[2] = {-1e30f, -1e30f};
        float lrow[2] = {0.f, 0.f};

        for (int kt = 0; kt <= qt; kt++) {
            const int k0 = kt * 64;
            // prefetch K,V (overlaps previous iteration's MMA)
            float4 kreg[8], vreg[8];
#pragma unroll
            for (int i = 0; i < 8; i++) {
                int idx = tid + 128 * i;
                int c = idx >> 4, d4 = idx & 15;
                kreg[i] = *(const float4*)(Kg + (size_t)(k0 + c) * HS + d4 * 4);
                vreg[i] = *(const float4*)(Vg + (size_t)(k0 + c) * HS + d4 * 4);
            }
            __syncthreads();   // previous iteration's GEMMs done
#pragma unroll
            for (int i = 0; i < 8; i++) {
                int idx = tid + 128 * i;
                int c = idx >> 4, d4 = idx & 15;
                u32 h0, l0, h1, l1;
                split2(kreg[i].x, kreg[i].y, h0, l0);
                split2(kreg[i].z, kreg[i].w, h1, l1);
                *(u32*)(Khi + c * ST + d4 * 4)     = h0;
                *(u32*)(Khi + c * ST + d4 * 4 + 2) = h1;
                *(u32*)(Klo + c * ST + d4 * 4)     = l0;
                *(u32*)(Klo + c * ST + d4 * 4 + 2) = l1;
                float vv[4] = {vreg[i].x, vreg[i].y, vreg[i].z, vreg[i].w};
#pragma unroll
                for (int e = 0; e < 4; e++) {
                    bf h = __float2bfloat16(vv[e]);
                    Vhi[(d4 * 4 + e) * ST + c] = h;
                    Vlo[(d4 * 4 + e) * ST + c] = __float2bfloat16(vv[e] - __bfloat162float(h));
                }
            }
            __syncthreads();

            // ---- GEMM1: S = Q K^T ----
            float s[8][4];
#pragma unroll
            for (int t = 0; t < 8; t++)
#pragma unroll
                for (int i = 0; i < 4; i++) s[t][i] = 0.f;
#pragma unroll
            for (int k16 = 0; k16 < 4; k16++) {
#pragma unroll
                for (int t = 0; t < 8; t++) {
                    const bf* bb = Khi + (t * 8 + g) * ST + k16 * 16 + pp * 2;
                    u32 bh[2] = {*(const u32*)bb, *(const u32*)(bb + 8)};
                    const bf* bb2 = Klo + (t * 8 + g) * ST + k16 * 16 + pp * 2;
                    u32 bl2[2] = {*(const u32*)bb2, *(const u32*)(bb2 + 8)};
                    mma16816(s[t], qh[k16], bh);
                    mma16816(s[t], ql[k16], bh);
                    mma16816(s[t], qh[k16], bl2);
                }
            }

            // ---- scale + causal mask ----
#pragma unroll
            for (int t = 0; t < 8; t++)
#pragma unroll
                for (int i = 0; i < 4; i++) s[t][i] *= 0.03125f;   // 1024^-0.5
            if (kt == qt) {
                const int r0 = q0 + wid * 16 + g, r1 = r0 + 8;
#pragma unroll
                for (int t = 0; t < 8; t++) {
                    int c0 = k0 + t * 8 + pp * 2;
                    if (c0 > r0)     s[t][0] = -1e30f;
                    if (c0 + 1 > r0) s[t][1] = -1e30f;
                    if (c0 > r1)     s[t][2] = -1e30f;
                    if (c0 + 1 > r1) s[t][3] = -1e30f;
                }
            }

            // ---- online softmax ----
            float rmx[2] = {-1e30f, -1e30f};
#pragma unroll
            for (int t = 0; t < 8; t++) {
                rmx[0] = fmaxf(rmx[0], fmaxf(s[t][0], s[t][1]));
                rmx[1] = fmaxf(rmx[1], fmaxf(s[t][2], s[t][3]));
            }
            float scl[2], rs[2] = {0.f, 0.f};
#pragma unroll
            for (int r = 0; r < 2; r++) {
                rmx[r] = fmaxf(rmx[r], __shfl_xor_sync(0xffffffffu, rmx[r], 1));
                rmx[r] = fmaxf(rmx[r], __shfl_xor_sync(0xffffffffu, rmx[r], 2));
                float mn = fmaxf(mrow[r], rmx[r]);
                scl[r] = __expf(mrow[r] - mn);
                mrow[r] = mn;
            }
#pragma unroll
            for (int t = 0; t < 8; t++) {
                float p00 = __expf(s[t][0] - mrow[0]);
                float p01 = __expf(s[t][1] - mrow[0]);
                float p10 = __expf(s[t][2] - mrow[1]);
                float p11 = __expf(s[t][3] - mrow[1]);
                rs[0] += p00 + p01;
                rs[1] += p10 + p11;
                u32 hi, lo;
                split2(p00, p01, hi, lo);
                *(u32*)(Phi + (wid * 16 + g) * ST + t * 8 + pp * 2) = hi;
                *(u32*)(Plo + (wid * 16 + g) * ST + t * 8 + pp * 2) = lo;
                split2(p10, p11, hi, lo);
                *(u32*)(Phi + (wid * 16 + g + 8) * ST + t * 8 + pp * 2) = hi;
                *(u32*)(Plo + (wid * 16 + g + 8) * ST + t * 8 + pp * 2) = lo;
            }
#pragma unroll
            for (int r = 0; r < 2; r++) {
                rs[r] += __shfl_xor_sync(0xffffffffu, rs[r], 1);
                rs[r] += __shfl_xor_sync(0xffffffffu, rs[r], 2);
                lrow[r] = lrow[r] * scl[r] + rs[r];
            }
#pragma unroll
            for (int t = 0; t < 8; t++) {
                o[t][0] *= scl[0]; o[t][1] *= scl[0];
                o[t][2] *= scl[1]; o[t][3] *= scl[1];
            }
            __syncwarp();   // P smem writes visible to whole warp (A-frags read own band only)

            // ---- GEMM2: O += P V ----
#pragma unroll
            for (int c16 = 0; c16 < 4; c16++) {
                u32 ah[4], al[4];
                const bf* ba = Phi + (wid * 16 + g) * ST + c16 * 16 + pp * 2;
                ah[0] = *(const u32*)ba;
                ah[1] = *(const u32*)(ba + 8 * ST);
                ah[2] = *(const u32*)(ba + 8);
                ah[3] = *(const u32*)(ba + 8 * ST + 8);
                const bf* bb = Plo + (wid * 16 + g) * ST + c16 * 16 + pp * 2;
                al[0] = *(const u32*)bb;
                al[1] = *(const u32*)(bb + 8 * ST);
                al[2] = *(const u32*)(bb + 8);
                al[3] = *(const u32*)(bb + 8 * ST + 8);
#pragma unroll
                for (int t = 0; t < 8; t++) {
                    const bf* vb = Vhi + (t * 8 + g) * ST + c16 * 16 + pp * 2;
                    u32 bh[2] = {*(const u32*)vb, *(const u32*)(vb + 8)};
                    const bf* vb2 = Vlo + (t * 8 + g) * ST + c16 * 16 + pp * 2;
                    u32 bl2[2] = {*(const u32*)vb2, *(const u32*)(vb2 + 8)};
                    mma16816(o[t], ah, bh);
                    mma16816(o[t], al, bh);
                    mma16816(o[t], ah, bl2);
                }
            }
        } // kt

        // ---- epilogue ----
        const float inv0 = 1.f / lrow[0], inv1 = 1.f / lrow[1];
        float* Og = out + ((size_t)b * TSEQ + q0) * HS;
#pragma unroll
        for (int t = 0; t < 8; t++) {
            int row = wid * 16 + g, col = t * 8 + pp * 2;
            *(float2*)(Og + (size_t)row * HS + col) =
                make_float2(o[t][0] * inv0, o[t][1] * inv0);
            *(float2*)(Og + (size_t)(row + 8) * HS + col) =
                make_float2(o[t][2] * inv1, o[t][3] * inv1);
        }
    } // rep
}

// =============================================================================
extern "C" void kernel_launch(void* const* d_in, const int* in_sizes, int n_in,
                              void* d_out, int out_size)
{
    const float* xq  = (const float*)d_in[0];
    const float* xkv = (const float*)d_in[1];
    const float* Wq  = (const float*)d_in[2];
    const float* Wk  = (const float*)d_in[3];
    const float* Wv  = (const float*)d_in[4];
    float* out = (float*)d_out;

    cudaFuncSetAttribute(proj_kernel, cudaFuncAttributeMaxDynamicSharedMemorySize, P_SMEM);
    cudaFuncSetAttribute(attn_kernel, cudaFuncAttributeMaxDynamicSharedMemorySize, A_SMEM);

    proj_kernel<<<dim3(BT / 256, 3), 256, P_SMEM>>>(xq, xkv, Wq, Wk, Wv);

    attn_kernel<<<dim3(16, BATCH), 128, A_SMEM>>>(out);
}

// round 6
// speedup vs baseline: 2.3769x; 1.1555x over previous
#include <cuda_runtime.h>
#include <cuda_bf16.h>
#include <math_constants.h>

typedef unsigned int u32;
typedef __nv_bfloat16 bf;

// Problem constants
#define BATCH 8
#define TSEQ  2048
#define CDIM  1024
#define HS    64
#define BT    (BATCH * TSEQ)   // 16384

// Scratch for projected Q, K, V — __device__ globals per allocation rules.
__device__ float g_q[BT * HS];
__device__ float g_k[BT * HS];
__device__ float g_v[BT * HS];

// ---------------- bf16 mma.sync (legacy HMMA path — baseline PTX on sm_103) -----
__device__ __forceinline__ void mma16816(float* d, const u32* a, const u32* b) {
    asm volatile(
        "mma.sync.aligned.m16n8k16.row.col.f32.bf16.bf16.f32 "
        "{%0,%1,%2,%3}, {%4,%5,%6,%7}, {%8,%9}, {%0,%1,%2,%3};"
        : "+f"(d[0]), "+f"(d[1]), "+f"(d[2]), "+f"(d[3])
        : "r"(a[0]), "r"(a[1]), "r"(a[2]), "r"(a[3]), "r"(b[0]), "r"(b[1]));
}

__device__ __forceinline__ void ldsm4(u32& r0, u32& r1, u32& r2, u32& r3, u32 addr) {
    asm volatile("ldmatrix.sync.aligned.m8n8.x4.shared.b16 {%0,%1,%2,%3}, [%4];"
                 : "=r"(r0), "=r"(r1), "=r"(r2), "=r"(r3) : "r"(addr));
}
__device__ __forceinline__ void ldsm4t(u32& r0, u32& r1, u32& r2, u32& r3, u32 addr) {
    asm volatile("ldmatrix.sync.aligned.m8n8.x4.trans.shared.b16 {%0,%1,%2,%3}, [%4];"
                 : "=r"(r0), "=r"(r1), "=r"(r2), "=r"(r3) : "r"(addr));
}
__device__ __forceinline__ u32 smem_u32(const void* p) {
    u32 a; asm("{ .reg .u64 t; cvta.to.shared.u64 t, %1; cvt.u32.u64 %0, t; }"
               : "=r"(a) : "l"(p));
    return a;
}

// Split two fp32 into packed-bf16 hi and lo words (x = hi + lo, ~16 mantissa bits)
__device__ __forceinline__ void split2(float x0, float x1, u32& hi, u32& lo) {
    __nv_bfloat162 h = __floats2bfloat162_rn(x0, x1);
    float r0 = x0 - __bfloat162float(h.x);
    float r1 = x1 - __bfloat162float(h.y);
    __nv_bfloat162 lw = __floats2bfloat162_rn(r0, r1);
    hi = *(u32*)&h;
    lo = *(u32*)&lw;
}

// smem row stride: 64 data + 8 pad = 72 bf16 (144B). ldmatrix rows land on
// banks 4*r mod 32 -> conflict-free.
#define ST 72

// =============================================================================
// Projection: Y[16384,64] = X[16384,1024] @ W[1024,64], blockIdx.y -> {Q,K,V}
// CTA: 128 threads (4 warps), tile 128(M) x 64(N), K chunked by 64.
// Warp: 32 rows (2 x m16), all 8 n8 tiles. 3-pass split-bf16. 3 CTAs/SM.
// =============================================================================
#define P_AHI 0
#define P_ALO (128 * ST * 2)                  // 18432
#define P_BHI (2 * 128 * ST * 2)              // 36864
#define P_BLO (P_BHI + 64 * ST * 2)           // 46080
#define P_SMEM (P_BHI + 2 * 64 * ST * 2)      // 55296

__global__ __launch_bounds__(128, 3)
void proj_kernel(const float* __restrict__ xq, const float* __restrict__ xkv,
                 const float* __restrict__ Wq, const float* __restrict__ Wk,
                 const float* __restrict__ Wv)
{
    extern __shared__ char dsm[];
    bf* Ahi = (bf*)(dsm + P_AHI); bf* Alo = (bf*)(dsm + P_ALO);
    bf* Bhi = (bf*)(dsm + P_BHI); bf* Blo = (bf*)(dsm + P_BLO);
    const u32 sAhi = smem_u32(Ahi), sAlo = smem_u32(Alo);
    const u32 sBhi = smem_u32(Bhi), sBlo = smem_u32(Blo);

    const int tid = threadIdx.x, wid = tid >> 5, l = tid & 31;
    const int g = l >> 2, pp = l & 3;
    const int lr = l & 7, lb8 = (l >> 3) & 1, lb16 = l >> 4;

    const float* X; const float* W; float* Y;
    if (blockIdx.y == 0)      { X = xq;  W = Wq; Y = g_q; }
    else if (blockIdx.y == 1) { X = xkv; W = Wk; Y = g_k; }
    else                      { X = xkv; W = Wv; Y = g_v; }

    const int m0 = blockIdx.x * 128;
    const float* Xp = X + (size_t)m0 * CDIM;

    float acc[2][8][4];
#pragma unroll
    for (int m = 0; m < 2; m++)
#pragma unroll
        for (int t = 0; t < 8; t++)
#pragma unroll
            for (int i = 0; i < 4; i++) acc[m][t][i] = 0.f;

    for (int ch = 0; ch < CDIM / 64; ch++) {
        const int k0 = ch * 64;
        __syncthreads();
        // A tile: 128 x 64 fp32 -> split -> smem (16 float4 / thread)
#pragma unroll 4
        for (int i = 0; i < 16; i++) {
            int idx = tid + 128 * i;
            int r = idx >> 4, k4 = idx & 15;
            float4 v = *(const float4*)(Xp + (size_t)r * CDIM + k0 + k4 * 4);
            u32 h0, l0, h1, l1;
            split2(v.x, v.y, h0, l0); split2(v.z, v.w, h1, l1);
            *(uint2*)(Ahi + r * ST + k4 * 4) = make_uint2(h0, h1);
            *(uint2*)(Alo + r * ST + k4 * 4) = make_uint2(l0, l1);
        }
        // B tile: W[k][n] -> transposed [n][k] (8 float4 / thread)
#pragma unroll
        for (int i = 0; i < 8; i++) {
            int idx = tid + 128 * i;
            int kk = idx >> 4, n4 = idx & 15;
            float4 v = *(const float4*)(W + (size_t)(k0 + kk) * HS + n4 * 4);
            float vv[4] = {v.x, v.y, v.z, v.w};
#pragma unroll
            for (int e = 0; e < 4; e++) {
                bf h = __float2bfloat16(vv[e]);
                Bhi[(n4 * 4 + e) * ST + kk] = h;
                Blo[(n4 * 4 + e) * ST + kk] = __float2bfloat16(vv[e] - __bfloat162float(h));
            }
        }
        __syncthreads();

#pragma unroll
        for (int k16 = 0; k16 < 4; k16++) {
            u32 ah[2][4], al[2][4];
#pragma unroll
            for (int m = 0; m < 2; m++) {
                u32 off = (u32)(((wid * 32 + m * 16 + lr + lb8 * 8) * ST
                               + k16 * 16 + lb16 * 8) * 2);
                ldsm4(ah[m][0], ah[m][1], ah[m][2], ah[m][3], sAhi + off);
                ldsm4(al[m][0], al[m][1], al[m][2], al[m][3], sAlo + off);
            }
#pragma unroll
            for (int tp = 0; tp < 4; tp++) {
                u32 off = (u32)(((16 * tp + lr + lb16 * 8) * ST
                               + k16 * 16 + lb8 * 8) * 2);
                u32 bh[4], bl[4];
                ldsm4(bh[0], bh[1], bh[2], bh[3], sBhi + off);
                ldsm4(bl[0], bl[1], bl[2], bl[3], sBlo + off);
#pragma unroll
                for (int m = 0; m < 2; m++) {
                    mma16816(acc[m][2 * tp],     ah[m], bh);
                    mma16816(acc[m][2 * tp],     al[m], bh);
                    mma16816(acc[m][2 * tp],     ah[m], bl);
                    mma16816(acc[m][2 * tp + 1], ah[m], bh + 2);
                    mma16816(acc[m][2 * tp + 1], al[m], bh + 2);
                    mma16816(acc[m][2 * tp + 1], ah[m], bl + 2);
                }
            }
        }
    }

#pragma unroll
    for (int m = 0; m < 2; m++)
#pragma unroll
        for (int t = 0; t < 8; t++) {
            int row = m0 + wid * 32 + m * 16 + g;
            int col = t * 8 + pp * 2;
            *(float2*)(Y + (size_t)row * HS + col)       = make_float2(acc[m][t][0], acc[m][t][1]);
            *(float2*)(Y + (size_t)(row + 8) * HS + col) = make_float2(acc[m][t][2], acc[m][t][3]);
        }
}

// =============================================================================
// Flash attention: one 64-row q-tile per CTA, 256 CTAs, 128 threads (4 warps),
// 2 CTAs/SM. bid -> (qt, batch) chosen so co-resident CTAs (bid, bid+148,
// placement = LUT[bid % 148]) have complementary work (qt=j pairs with 26-j,
// sums to 28) and the 40 solo SMs get the heaviest tiles (qt 27..31).
// =============================================================================
#define A_QHI 0
#define A_QLO 9216
#define A_KHI 18432
#define A_KLO 27648
#define A_VHI 36864
#define A_VLO 46080
#define A_PHI 55296
#define A_PLO 64512
#define A_SMEM 73728

__global__ __launch_bounds__(128, 2)
void attn_kernel(float* __restrict__ out)
{
    extern __shared__ char dsm[];
    bf* Qhi = (bf*)(dsm + A_QHI); bf* Qlo = (bf*)(dsm + A_QLO);
    bf* Khi = (bf*)(dsm + A_KHI); bf* Klo = (bf*)(dsm + A_KLO);
    bf* Vhi = (bf*)(dsm + A_VHI); bf* Vlo = (bf*)(dsm + A_VLO);
    bf* Phi = (bf*)(dsm + A_PHI); bf* Plo = (bf*)(dsm + A_PLO);
    const u32 sQhi = smem_u32(Qhi), sQlo = smem_u32(Qlo);
    const u32 sKhi = smem_u32(Khi), sKlo = smem_u32(Klo);
    const u32 sVhi = smem_u32(Vhi), sVlo = smem_u32(Vlo);
    const u32 sPhi = smem_u32(Phi), sPlo = smem_u32(Plo);

    const int tid = threadIdx.x, wid = tid >> 5, l = tid & 31;
    const int g = l >> 2, pp = l & 3;
    const int lr = l & 7, lb8 = (l >> 3) & 1, lb16 = l >> 4;

    // --- balanced bid -> (qt, batch) mapping ---
    int bid = blockIdx.x, qt, b;
    if (bid >= 108 && bid < 148) {
        int i = bid - 108;               // 40 solo-heavy tiles: qt 31..27
        qt = 31 - (i >> 3); b = i & 7;
    } else {
        int p = (bid < 108) ? bid : (bid - 148);
        bool second = (bid >= 148);
        if (p < 104) { int j = p >> 3; b = p & 7; qt = second ? (26 - j) : j; }
        else         { int q = p - 104; qt = 13; b = second ? (2 * q + 1) : (2 * q); }
    }
    const int q0 = qt * 64;

    const float* Qg = g_q + (size_t)b * TSEQ * HS;
    const float* Kg = g_k + (size_t)b * TSEQ * HS;
    const float* Vg = g_v + (size_t)b * TSEQ * HS;

    // load + split Q tile (8 float4 / thread)
#pragma unroll
    for (int i = 0; i < 8; i++) {
        int idx = tid + 128 * i;
        int r = idx >> 4, d4 = idx & 15;
        float4 v = *(const float4*)(Qg + (size_t)(q0 + r) * HS + d4 * 4);
        u32 h0, l0, h1, l1;
        split2(v.x, v.y, h0, l0); split2(v.z, v.w, h1, l1);
        *(uint2*)(Qhi + r * ST + d4 * 4) = make_uint2(h0, h1);
        *(uint2*)(Qlo + r * ST + d4 * 4) = make_uint2(l0, l1);
    }
    __syncthreads();

    // hoist Q fragments (a-frags) via ldmatrix
    u32 qh[4][4], ql[4][4];
#pragma unroll
    for (int k16 = 0; k16 < 4; k16++) {
        u32 off = (u32)(((wid * 16 + lr + lb8 * 8) * ST + k16 * 16 + lb16 * 8) * 2);
        ldsm4(qh[k16][0], qh[k16][1], qh[k16][2], qh[k16][3], sQhi + off);
        ldsm4(ql[k16][0], ql[k16][1], ql[k16][2], ql[k16][3], sQlo + off);
    }

    float o[8][4];
#pragma unroll
    for (int t = 0; t < 8; t++)
#pragma unroll
        for (int i = 0; i < 4; i++) o[t][i] = 0.f;
    float mrow[2] = {-1e30f, -1e30f};
    float lrow[2] = {0.f, 0.f};

    for (int kt = 0; kt <= qt; kt++) {
        const int k0 = kt * 64;
        // prefetch K,V (overlaps previous iteration's MMA)
        float4 kreg[8], vreg[8];
#pragma unroll
        for (int i = 0; i < 8; i++) {
            int idx = tid + 128 * i;
            int c = idx >> 4, d4 = idx & 15;
            kreg[i] = *(const float4*)(Kg + (size_t)(k0 + c) * HS + d4 * 4);
            vreg[i] = *(const float4*)(Vg + (size_t)(k0 + c) * HS + d4 * 4);
        }
        __syncthreads();   // previous iteration's GEMMs done
#pragma unroll
        for (int i = 0; i < 8; i++) {
            int idx = tid + 128 * i;
            int c = idx >> 4, d4 = idx & 15;
            u32 h0, l0, h1, l1;
            split2(kreg[i].x, kreg[i].y, h0, l0);
            split2(kreg[i].z, kreg[i].w, h1, l1);
            *(uint2*)(Khi + c * ST + d4 * 4) = make_uint2(h0, h1);
            *(uint2*)(Klo + c * ST + d4 * 4) = make_uint2(l0, l1);
            split2(vreg[i].x, vreg[i].y, h0, l0);
            split2(vreg[i].z, vreg[i].w, h1, l1);
            *(uint2*)(Vhi + c * ST + d4 * 4) = make_uint2(h0, h1);   // row-major [s][h]
            *(uint2*)(Vlo + c * ST + d4 * 4) = make_uint2(l0, l1);
        }
        __syncthreads();

        // ---- GEMM1: S = Q K^T ----
        float s[8][4];
#pragma unroll
        for (int t = 0; t < 8; t++)
#pragma unroll
            for (int i = 0; i < 4; i++) s[t][i] = 0.f;
#pragma unroll
        for (int k16 = 0; k16 < 4; k16++) {
#pragma unroll
            for (int tp = 0; tp < 4; tp++) {
                u32 off = (u32)(((16 * tp + lr + lb16 * 8) * ST + k16 * 16 + lb8 * 8) * 2);
                u32 bh[4], bl[4];
                ldsm4(bh[0], bh[1], bh[2], bh[3], sKhi + off);
                ldsm4(bl[0], bl[1], bl[2], bl[3], sKlo + off);
                mma16816(s[2 * tp],     qh[k16], bh);
                mma16816(s[2 * tp],     ql[k16], bh);
                mma16816(s[2 * tp],     qh[k16], bl);
                mma16816(s[2 * tp + 1], qh[k16], bh + 2);
                mma16816(s[2 * tp + 1], ql[k16], bh + 2);
                mma16816(s[2 * tp + 1], qh[k16], bl + 2);
            }
        }

        // ---- scale + causal mask ----
#pragma unroll
        for (int t = 0; t < 8; t++)
#pragma unroll
            for (int i = 0; i < 4; i++) s[t][i] *= 0.03125f;   // 1024^-0.5
        if (kt == qt) {
            const int r0 = q0 + wid * 16 + g, r1 = r0 + 8;
#pragma unroll
            for (int t = 0; t < 8; t++) {
                int c0 = k0 + t * 8 + pp * 2;
                if (c0 > r0)     s[t][0] = -1e30f;
                if (c0 + 1 > r0) s[t][1] = -1e30f;
                if (c0 > r1)     s[t][2] = -1e30f;
                if (c0 + 1 > r1) s[t][3] = -1e30f;
            }
        }

        // ---- online softmax ----
        float rmx[2] = {-1e30f, -1e30f};
#pragma unroll
        for (int t = 0; t < 8; t++) {
            rmx[0] = fmaxf(rmx[0], fmaxf(s[t][0], s[t][1]));
            rmx[1] = fmaxf(rmx[1], fmaxf(s[t][2], s[t][3]));
        }
        float scl[2], rs[2] = {0.f, 0.f};
#pragma unroll
        for (int r = 0; r < 2; r++) {
            rmx[r] = fmaxf(rmx[r], __shfl_xor_sync(0xffffffffu, rmx[r], 1));
            rmx[r] = fmaxf(rmx[r], __shfl_xor_sync(0xffffffffu, rmx[r], 2));
            float mn = fmaxf(mrow[r], rmx[r]);
            scl[r] = __expf(mrow[r] - mn);
            mrow[r] = mn;
        }
#pragma unroll
        for (int t = 0; t < 8; t++) {
            float p00 = __expf(s[t][0] - mrow[0]);
            float p01 = __expf(s[t][1] - mrow[0]);
            float p10 = __expf(s[t][2] - mrow[1]);
            float p11 = __expf(s[t][3] - mrow[1]);
            rs[0] += p00 + p01;
            rs[1] += p10 + p11;
            u32 hi, lo;
            split2(p00, p01, hi, lo);
            *(u32*)(Phi + (wid * 16 + g) * ST + t * 8 + pp * 2) = hi;
            *(u32*)(Plo + (wid * 16 + g) * ST + t * 8 + pp * 2) = lo;
            split2(p10, p11, hi, lo);
            *(u32*)(Phi + (wid * 16 + g + 8) * ST + t * 8 + pp * 2) = hi;
            *(u32*)(Plo + (wid * 16 + g + 8) * ST + t * 8 + pp * 2) = lo;
        }
#pragma unroll
        for (int r = 0; r < 2; r++) {
            rs[r] += __shfl_xor_sync(0xffffffffu, rs[r], 1);
            rs[r] += __shfl_xor_sync(0xffffffffu, rs[r], 2);
            lrow[r] = lrow[r] * scl[r] + rs[r];
        }
#pragma unroll
        for (int t = 0; t < 8; t++) {
            o[t][0] *= scl[0]; o[t][1] *= scl[0];
            o[t][2] *= scl[1]; o[t][3] *= scl[1];
        }
        __syncwarp();   // P writes are warp-local (rows wid*16..wid*16+15)

        // ---- GEMM2: O += P V  (V B-frags via ldmatrix.trans on row-major V) ----
#pragma unroll
        for (int c16 = 0; c16 < 4; c16++) {
            u32 aoff = (u32)(((wid * 16 + lr + lb8 * 8) * ST + c16 * 16 + lb16 * 8) * 2);
            u32 ph[4], pl[4];
            ldsm4(ph[0], ph[1], ph[2], ph[3], sPhi + aoff);
            ldsm4(pl[0], pl[1], pl[2], pl[3], sPlo + aoff);
#pragma unroll
            for (int tp = 0; tp < 4; tp++) {
                u32 voff = (u32)(((c16 * 16 + lr + lb8 * 8) * ST + 16 * tp + lb16 * 8) * 2);
                u32 vh[4], vl[4];
                ldsm4t(vh[0], vh[1], vh[2], vh[3], sVhi + voff);
                ldsm4t(vl[0], vl[1], vl[2], vl[3], sVlo + voff);
                mma16816(o[2 * tp],     ph, vh);
                mma16816(o[2 * tp],     pl, vh);
                mma16816(o[2 * tp],     ph, vl);
                mma16816(o[2 * tp + 1], ph, vh + 2);
                mma16816(o[2 * tp + 1], pl, vh + 2);
                mma16816(o[2 * tp + 1], ph, vl + 2);
            }
        }
    } // kt

    // ---- epilogue ----
    const float inv0 = 1.f / lrow[0], inv1 = 1.f / lrow[1];
    float* Og = out + ((size_t)b * TSEQ + q0) * HS;
#pragma unroll
    for (int t = 0; t < 8; t++) {
        int row = wid * 16 + g, col = t * 8 + pp * 2;
        *(float2*)(Og + (size_t)row * HS + col) =
            make_float2(o[t][0] * inv0, o[t][1] * inv0);
        *(float2*)(Og + (size_t)(row + 8) * HS + col) =
            make_float2(o[t][2] * inv1, o[t][3] * inv1);
    }
}

// =============================================================================
extern "C" void kernel_launch(void* const* d_in, const int* in_sizes, int n_in,
                              void* d_out, int out_size)
{
    const float* xq  = (const float*)d_in[0];
    const float* xkv = (const float*)d_in[1];
    const float* Wq  = (const float*)d_in[2];
    const float* Wk  = (const float*)d_in[3];
    const float* Wv  = (const float*)d_in[4];
    float* out = (float*)d_out;

    cudaFuncSetAttribute(proj_kernel, cudaFuncAttributeMaxDynamicSharedMemorySize, P_SMEM);
    cudaFuncSetAttribute(attn_kernel, cudaFuncAttributeMaxDynamicSharedMemorySize, A_SMEM);

    proj_kernel<<<dim3(BT / 128, 3), 128, P_SMEM>>>(xq, xkv, Wq, Wk, Wv);

    attn_kernel<<<256, 128, A_SMEM>>>(out);
}

// round 7
// speedup vs baseline: 2.9602x; 1.2454x over previous
#include <cuda_runtime.h>
#include <cuda_bf16.h>
#include <math_constants.h>

typedef unsigned int u32;
typedef __nv_bfloat16 bf;

// Problem constants
#define BATCH 8
#define TSEQ  2048
#define CDIM  1024
#define HS    64
#define BT    (BATCH * TSEQ)   // 16384

// Pre-split bf16 hi/lo scratch — __device__ globals per allocation rules.
__device__ bf g_qhi[BT * HS], g_qlo[BT * HS];
__device__ bf g_khi[BT * HS], g_klo[BT * HS];
__device__ bf g_vhi[BT * HS], g_vlo[BT * HS];
__device__ bf g_whi[3 * CDIM * HS], g_wlo[3 * CDIM * HS];   // order Q,K,V

// ---------------- bf16 mma.sync (legacy HMMA path — baseline PTX on sm_103) -----
__device__ __forceinline__ void mma16816(float* d, const u32* a, const u32* b) {
    asm volatile(
        "mma.sync.aligned.m16n8k16.row.col.f32.bf16.bf16.f32 "
        "{%0,%1,%2,%3}, {%4,%5,%6,%7}, {%8,%9}, {%0,%1,%2,%3};"
        : "+f"(d[0]), "+f"(d[1]), "+f"(d[2]), "+f"(d[3])
        : "r"(a[0]), "r"(a[1]), "r"(a[2]), "r"(a[3]), "r"(b[0]), "r"(b[1]));
}
__device__ __forceinline__ void ldsm4(u32& r0, u32& r1, u32& r2, u32& r3, u32 addr) {
    asm volatile("ldmatrix.sync.aligned.m8n8.x4.shared.b16 {%0,%1,%2,%3}, [%4];"
                 : "=r"(r0), "=r"(r1), "=r"(r2), "=r"(r3) : "r"(addr));
}
__device__ __forceinline__ void ldsm4t(u32& r0, u32& r1, u32& r2, u32& r3, u32 addr) {
    asm volatile("ldmatrix.sync.aligned.m8n8.x4.trans.shared.b16 {%0,%1,%2,%3}, [%4];"
                 : "=r"(r0), "=r"(r1), "=r"(r2), "=r"(r3) : "r"(addr));
}
__device__ __forceinline__ u32 smem_u32(const void* p) {
    u32 a; asm("{ .reg .u64 t; cvta.to.shared.u64 t, %1; cvt.u32.u64 %0, t; }"
               : "=r"(a) : "l"(p));
    return a;
}

// Split two fp32 into packed-bf16 hi and lo words (x = hi + lo, ~16 mantissa bits)
__device__ __forceinline__ void split2(float x0, float x1, u32& hi, u32& lo) {
    __nv_bfloat162 h = __floats2bfloat162_rn(x0, x1);
    float r0 = x0 - __bfloat162float(h.x);
    float r1 = x1 - __bfloat162float(h.y);
    __nv_bfloat162 lw = __floats2bfloat162_rn(r0, r1);
    hi = *(u32*)&h;
    lo = *(u32*)&lw;
}

// smem row stride: 64 data + 8 pad = 72 bf16 (144B) -> ldmatrix conflict-free.
#define ST  72
// KV-path B tile stride: 128 data + 8 pad = 136 bf16 (272B), same 4r bank walk.
#define STB 136

// =============================================================================
// W pre-split: 3 x [1024 x 64] fp32 -> bf16 hi/lo. Tiny, runs once.
// =============================================================================
__global__ __launch_bounds__(256)
void wsplit_kernel(const float* __restrict__ Wq, const float* __restrict__ Wk,
                   const float* __restrict__ Wv)
{
    int base = (blockIdx.x * 256 + threadIdx.x) * 8;   // 96 CTAs cover 196608 elems
#pragma unroll
    for (int e = 0; e < 8; e += 2) {
        int idx = base + e;
        int mat = idx >> 16, rem = idx & 65535;
        const float* W = (mat == 0) ? Wq : (mat == 1) ? Wk : Wv;
        float2 v = *(const float2*)(W + rem);
        u32 hi, lo;
        split2(v.x, v.y, hi, lo);
        *(u32*)(g_whi + idx) = hi;
        *(u32*)(g_wlo + idx) = lo;
    }
}

// =============================================================================
// Projection. Grid 384: bid<128 -> Q path (M=128, N=64, x_q);
// bid>=128 -> KV path (M=64, N=128 = [K|V], x_kv, shared A split).
// Equal MMA work per CTA (48 HMMA per k16). 3 CTAs/SM.
// B tiles copied as pre-split bf16 in [k][n] layout; b-frags via ldmatrix.trans.
// =============================================================================
#define PQ_ALO (128 * ST * 2)           // 18432
#define PQ_B   (2 * 128 * ST * 2)       // 36864
#define PQ_BLO (PQ_B + 64 * ST * 2)     // 46080
#define P_SMEM 55296
#define W_K_OFF (CDIM * HS)
#define W_V_OFF (2 * CDIM * HS)

__global__ __launch_bounds__(128, 3)
void proj_kernel(const float* __restrict__ xq, const float* __restrict__ xkv)
{
    extern __shared__ char dsm[];
    const int tid = threadIdx.x, wid = tid >> 5, l = tid & 31;
    const int g = l >> 2, pp = l & 3;
    const int lr = l & 7, lb8 = (l >> 3) & 1, lb16 = l >> 4;
    const int bid = blockIdx.x;

    if (bid < 128) {
        // ---------------- Q path: M=128, N=64 ----------------
        bf* Ahi = (bf*)dsm;            bf* Alo = (bf*)(dsm + PQ_ALO);
        bf* Bhi = (bf*)(dsm + PQ_B);   bf* Blo = (bf*)(dsm + PQ_BLO);
        const u32 sAhi = smem_u32(Ahi), sAlo = smem_u32(Alo);
        const u32 sBhi = smem_u32(Bhi), sBlo = smem_u32(Blo);
        const int m0 = bid * 128;
        const float* Xp = xq + (size_t)m0 * CDIM;

        float acc[2][8][4];
#pragma unroll
        for (int m = 0; m < 2; m++)
#pragma unroll
            for (int t = 0; t < 8; t++)
#pragma unroll
                for (int i = 0; i < 4; i++) acc[m][t][i] = 0.f;

        for (int ch = 0; ch < CDIM / 64; ch++) {
            const int k0 = ch * 64;
            __syncthreads();
            // A: 128x64 fp32 -> split -> smem
#pragma unroll 4
            for (int i = 0; i < 16; i++) {
                int idx = tid + 128 * i;
                int r = idx >> 4, c4 = idx & 15;
                float4 v = *(const float4*)(Xp + (size_t)r * CDIM + k0 + c4 * 4);
                u32 h0, l0, h1, l1;
                split2(v.x, v.y, h0, l0); split2(v.z, v.w, h1, l1);
                *(uint2*)(Ahi + r * ST + c4 * 4) = make_uint2(h0, h1);
                *(uint2*)(Alo + r * ST + c4 * 4) = make_uint2(l0, l1);
            }
            // B: pre-split Wq bf16, [k][n] layout, straight uint4 copy
#pragma unroll
            for (int i = 0; i < 8; i++) {
                int idx = tid + 128 * i;
                int arr = idx >> 9, rem = idx & 511;
                int k = rem >> 3, seg = rem & 7;
                const bf* src = (arr ? g_wlo : g_whi) + (size_t)(k0 + k) * HS + seg * 8;
                bf* dst = (arr ? Blo : Bhi) + k * ST + seg * 8;
                *(uint4*)dst = *(const uint4*)src;
            }
            __syncthreads();

#pragma unroll
            for (int k16 = 0; k16 < 4; k16++) {
                u32 ah[2][4], al[2][4];
#pragma unroll
                for (int m = 0; m < 2; m++) {
                    u32 off = (u32)(((wid * 32 + m * 16 + lr + lb8 * 8) * ST
                                   + k16 * 16 + lb16 * 8) * 2);
                    ldsm4(ah[m][0], ah[m][1], ah[m][2], ah[m][3], sAhi + off);
                    ldsm4(al[m][0], al[m][1], al[m][2], al[m][3], sAlo + off);
                }
#pragma unroll
                for (int tp = 0; tp < 4; tp++) {
                    u32 boff = (u32)(((k16 * 16 + lr + lb8 * 8) * ST
                                    + tp * 16 + lb16 * 8) * 2);
                    u32 bh[4], bl[4];
                    ldsm4t(bh[0], bh[1], bh[2], bh[3], sBhi + boff);
                    ldsm4t(bl[0], bl[1], bl[2], bl[3], sBlo + boff);
#pragma unroll
                    for (int m = 0; m < 2; m++) {
                        mma16816(acc[m][2 * tp],     ah[m], bh);
                        mma16816(acc[m][2 * tp],     al[m], bh);
                        mma16816(acc[m][2 * tp],     ah[m], bl);
                        mma16816(acc[m][2 * tp + 1], ah[m], bh + 2);
                        mma16816(acc[m][2 * tp + 1], al[m], bh + 2);
                        mma16816(acc[m][2 * tp + 1], ah[m], bl + 2);
                    }
                }
            }
        }
        // epilogue: split fp32 accs -> g_qhi/g_qlo
#pragma unroll
        for (int m = 0; m < 2; m++)
#pragma unroll
            for (int t = 0; t < 8; t++) {
                int row = m0 + wid * 32 + m * 16 + g;
                int col = t * 8 + pp * 2;
                u32 hi, lo;
                split2(acc[m][t][0], acc[m][t][1], hi, lo);
                *(u32*)(g_qhi + (size_t)row * HS + col) = hi;
                *(u32*)(g_qlo + (size_t)row * HS + col) = lo;
                split2(acc[m][t][2], acc[m][t][3], hi, lo);
                *(u32*)(g_qhi + (size_t)(row + 8) * HS + col) = hi;
                *(u32*)(g_qlo + (size_t)(row + 8) * HS + col) = lo;
            }
    } else {
        // ---------------- KV path: M=64, N=128 ([K|V]) ----------------
        bf* Ahi = (bf*)dsm;                    bf* Alo = (bf*)(dsm + 64 * ST * 2);
        bf* Bhi = (bf*)(dsm + 2 * 64 * ST * 2);
        bf* Blo = (bf*)(dsm + 2 * 64 * ST * 2 + 64 * STB * 2);
        const u32 sAhi = smem_u32(Ahi), sAlo = smem_u32(Alo);
        const u32 sBhi = smem_u32(Bhi), sBlo = smem_u32(Blo);
        const int m0 = (bid - 128) * 64;
        const float* Xp = xkv + (size_t)m0 * CDIM;

        float acc[16][4];
#pragma unroll
        for (int t = 0; t < 16; t++)
#pragma unroll
            for (int i = 0; i < 4; i++) acc[t][i] = 0.f;

        for (int ch = 0; ch < CDIM / 64; ch++) {
            const int k0 = ch * 64;
            __syncthreads();
            // A: 64x64 fp32 -> split -> smem
#pragma unroll
            for (int i = 0; i < 8; i++) {
                int idx = tid + 128 * i;
                int r = idx >> 4, c4 = idx & 15;
                float4 v = *(const float4*)(Xp + (size_t)r * CDIM + k0 + c4 * 4);
                u32 h0, l0, h1, l1;
                split2(v.x, v.y, h0, l0); split2(v.z, v.w, h1, l1);
                *(uint2*)(Ahi + r * ST + c4 * 4) = make_uint2(h0, h1);
                *(uint2*)(Alo + r * ST + c4 * 4) = make_uint2(l0, l1);
            }
            // B: [k][0..63]=Wk, [k][64..127]=Wv, pre-split bf16 copy
#pragma unroll
            for (int i = 0; i < 16; i++) {
                int idx = tid + 128 * i;
                int arr = idx >> 10, rem = idx & 1023;
                int k = rem >> 4, seg = rem & 15;
                size_t woff = (seg < 8)
                    ? (W_K_OFF + (size_t)(k0 + k) * HS + seg * 8)
                    : (W_V_OFF + (size_t)(k0 + k) * HS + (seg - 8) * 8);
                const bf* src = (arr ? g_wlo : g_whi) + woff;
                bf* dst = (arr ? Blo : Bhi) + k * STB + seg * 8;
                *(uint4*)dst = *(const uint4*)src;
            }
            __syncthreads();

#pragma unroll
            for (int k16 = 0; k16 < 4; k16++) {
                u32 ah[4], al[4];
                u32 aoff = (u32)(((wid * 16 + lr + lb8 * 8) * ST
                                + k16 * 16 + lb16 * 8) * 2);
                ldsm4(ah[0], ah[1], ah[2], ah[3], sAhi + aoff);
                ldsm4(al[0], al[1], al[2], al[3], sAlo + aoff);
#pragma unroll
                for (int tp = 0; tp < 8; tp++) {
                    u32 boff = (u32)(((k16 * 16 + lr + lb8 * 8) * STB
                                    + tp * 16 + lb16 * 8) * 2);
                    u32 bh[4], bl[4];
                    ldsm4t(bh[0], bh[1], bh[2], bh[3], sBhi + boff);
                    ldsm4t(bl[0], bl[1], bl[2], bl[3], sBlo + boff);
                    mma16816(acc[2 * tp],     ah, bh);
                    mma16816(acc[2 * tp],     al, bh);
                    mma16816(acc[2 * tp],     ah, bl);
                    mma16816(acc[2 * tp + 1], ah, bh + 2);
                    mma16816(acc[2 * tp + 1], al, bh + 2);
                    mma16816(acc[2 * tp + 1], ah, bl + 2);
                }
            }
        }
        // epilogue: t<8 -> K, t>=8 -> V
#pragma unroll
        for (int t = 0; t < 16; t++) {
            int row = m0 + wid * 16 + g;
            int col = (t & 7) * 8 + pp * 2;
            bf* Dhi = (t < 8) ? g_khi : g_vhi;
            bf* Dlo = (t < 8) ? g_klo : g_vlo;
            u32 hi, lo;
            split2(acc[t][0], acc[t][1], hi, lo);
            *(u32*)(Dhi + (size_t)row * HS + col) = hi;
            *(u32*)(Dlo + (size_t)row * HS + col) = lo;
            split2(acc[t][2], acc[t][3], hi, lo);
            *(u32*)(Dhi + (size_t)(row + 8) * HS + col) = hi;
            *(u32*)(Dlo + (size_t)(row + 8) * HS + col) = lo;
        }
    }
}

// =============================================================================
// Flash attention: one 64-row q-tile per CTA, 256 CTAs, 128 threads, 2 CTAs/SM.
// Q/K/V arrive pre-split bf16 -> phase L is pure LDG.128 + STS.128.
// Balanced bid->(qt,batch): co-resident pairs (bid, bid+148) sum to 28 work
// units; the 40 solo SMs get the heaviest tiles (qt 27..31).
// =============================================================================
#define A_QHI 0
#define A_QLO 9216
#define A_KHI 18432
#define A_KLO 27648
#define A_VHI 36864
#define A_VLO 46080
#define A_PHI 55296
#define A_PLO 64512
#define A_SMEM 73728

__global__ __launch_bounds__(128, 2)
void attn_kernel(float* __restrict__ out)
{
    extern __shared__ char dsm[];
    bf* Qhi = (bf*)(dsm + A_QHI); bf* Qlo = (bf*)(dsm + A_QLO);
    bf* Khi = (bf*)(dsm + A_KHI); bf* Klo = (bf*)(dsm + A_KLO);
    bf* Vhi = (bf*)(dsm + A_VHI); bf* Vlo = (bf*)(dsm + A_VLO);
    bf* Phi = (bf*)(dsm + A_PHI); bf* Plo = (bf*)(dsm + A_PLO);
    const u32 sQhi = smem_u32(Qhi), sQlo = smem_u32(Qlo);
    const u32 sKhi = smem_u32(Khi), sKlo = smem_u32(Klo);
    const u32 sVhi = smem_u32(Vhi), sVlo = smem_u32(Vlo);
    const u32 sPhi = smem_u32(Phi), sPlo = smem_u32(Plo);

    const int tid = threadIdx.x, wid = tid >> 5, l = tid & 31;
    const int g = l >> 2, pp = l & 3;
    const int lr = l & 7, lb8 = (l >> 3) & 1, lb16 = l >> 4;

    // --- balanced bid -> (qt, batch) mapping ---
    int bid = blockIdx.x, qt, b;
    if (bid >= 108 && bid < 148) {
        int i = bid - 108;               // 40 solo-heavy tiles: qt 31..27
        qt = 31 - (i >> 3); b = i & 7;
    } else {
        int p = (bid < 108) ? bid : (bid - 148);
        bool second = (bid >= 148);
        if (p < 104) { int j = p >> 3; b = p & 7; qt = second ? (26 - j) : j; }
        else         { int q = p - 104; qt = 13; b = second ? (2 * q + 1) : (2 * q); }
    }
    const int q0 = qt * 64;

    const bf* QgH = g_qhi + (size_t)b * TSEQ * HS;
    const bf* QgL = g_qlo + (size_t)b * TSEQ * HS;
    const bf* KgH = g_khi + (size_t)b * TSEQ * HS;
    const bf* KgL = g_klo + (size_t)b * TSEQ * HS;
    const bf* VgH = g_vhi + (size_t)b * TSEQ * HS;
    const bf* VgL = g_vlo + (size_t)b * TSEQ * HS;

    // Q tile: straight bf16 copy (8 uint4 / thread)
#pragma unroll
    for (int i = 0; i < 8; i++) {
        int idx = tid + 128 * i;
        int arr = idx >> 9, rem = idx & 511;
        int r = rem >> 3, seg = rem & 7;
        const bf* src = (arr ? QgL : QgH) + (size_t)(q0 + r) * HS + seg * 8;
        bf* dst = (arr ? Qlo : Qhi) + r * ST + seg * 8;
        *(uint4*)dst = *(const uint4*)src;
    }
    __syncthreads();

    // hoist Q a-frags
    u32 qh[4][4], ql[4][4];
#pragma unroll
    for (int k16 = 0; k16 < 4; k16++) {
        u32 off = (u32)(((wid * 16 + lr + lb8 * 8) * ST + k16 * 16 + lb16 * 8) * 2);
        ldsm4(qh[k16][0], qh[k16][1], qh[k16][2], qh[k16][3], sQhi + off);
        ldsm4(ql[k16][0], ql[k16][1], ql[k16][2], ql[k16][3], sQlo + off);
    }

    float o[8][4];
#pragma unroll
    for (int t = 0; t < 8; t++)
#pragma unroll
        for (int i = 0; i < 4; i++) o[t][i] = 0.f;
    float mrow[2] = {-1e30f, -1e30f};
    float lrow[2] = {0.f, 0.f};

    for (int kt = 0; kt <= qt; kt++) {
        const int k0 = kt * 64;
        // prefetch K/V hi+lo (16 uint4) — overlaps previous iteration's MMA
        uint4 kv[16];
#pragma unroll
        for (int i = 0; i < 16; i++) {
            int idx = tid + 128 * i;
            int arr = idx >> 9, rem = idx & 511;
            int r = rem >> 3, seg = rem & 7;
            const bf* src = (arr == 0 ? KgH : arr == 1 ? KgL : arr == 2 ? VgH : VgL)
                          + (size_t)(k0 + r) * HS + seg * 8;
            kv[i] = *(const uint4*)src;
        }
        __syncthreads();   // previous iteration's GEMMs done
#pragma unroll
        for (int i = 0; i < 16; i++) {
            int idx = tid + 128 * i;
            int arr = idx >> 9, rem = idx & 511;
            int r = rem >> 3, seg = rem & 7;
            bf* dst = (arr == 0 ? Khi : arr == 1 ? Klo : arr == 2 ? Vhi : Vlo)
                    + r * ST + seg * 8;
            *(uint4*)dst = kv[i];
        }
        __syncthreads();

        // ---- GEMM1: S = Q K^T ----
        float s[8][4];
#pragma unroll
        for (int t = 0; t < 8; t++)
#pragma unroll
            for (int i = 0; i < 4; i++) s[t][i] = 0.f;
#pragma unroll
        for (int k16 = 0; k16 < 4; k16++) {
#pragma unroll
            for (int tp = 0; tp < 4; tp++) {
                u32 off = (u32)(((16 * tp + lr + lb16 * 8) * ST + k16 * 16 + lb8 * 8) * 2);
                u32 bh[4], bl[4];
                ldsm4(bh[0], bh[1], bh[2], bh[3], sKhi + off);
                ldsm4(bl[0], bl[1], bl[2], bl[3], sKlo + off);
                mma16816(s[2 * tp],     qh[k16], bh);
                mma16816(s[2 * tp],     ql[k16], bh);
                mma16816(s[2 * tp],     qh[k16], bl);
                mma16816(s[2 * tp + 1], qh[k16], bh + 2);
                mma16816(s[2 * tp + 1], ql[k16], bh + 2);
                mma16816(s[2 * tp + 1], qh[k16], bl + 2);
            }
        }

        // ---- scale + causal mask ----
#pragma unroll
        for (int t = 0; t < 8; t++)
#pragma unroll
            for (int i = 0; i < 4; i++) s[t][i] *= 0.03125f;   // 1024^-0.5
        if (kt == qt) {
            const int r0 = q0 + wid * 16 + g, r1 = r0 + 8;
#pragma unroll
            for (int t = 0; t < 8; t++) {
                int c0 = k0 + t * 8 + pp * 2;
                if (c0 > r0)     s[t][0] = -1e30f;
                if (c0 + 1 > r0) s[t][1] = -1e30f;
                if (c0 > r1)     s[t][2] = -1e30f;
                if (c0 + 1 > r1) s[t][3] = -1e30f;
            }
        }

        // ---- online softmax ----
        float rmx[2] = {-1e30f, -1e30f};
#pragma unroll
        for (int t = 0; t < 8; t++) {
            rmx[0] = fmaxf(rmx[0], fmaxf(s[t][0], s[t][1]));
            rmx[1] = fmaxf(rmx[1], fmaxf(s[t][2], s[t][3]));
        }
        float scl[2], rs[2] = {0.f, 0.f};
#pragma unroll
        for (int r = 0; r < 2; r++) {
            rmx[r] = fmaxf(rmx[r], __shfl_xor_sync(0xffffffffu, rmx[r], 1));
            rmx[r] = fmaxf(rmx[r], __shfl_xor_sync(0xffffffffu, rmx[r], 2));
            float mn = fmaxf(mrow[r], rmx[r]);
            scl[r] = __expf(mrow[r] - mn);
            mrow[r] = mn;
        }
#pragma unroll
        for (int t = 0; t < 8; t++) {
            float p00 = __expf(s[t][0] - mrow[0]);
            float p01 = __expf(s[t][1] - mrow[0]);
            float p10 = __expf(s[t][2] - mrow[1]);
            float p11 = __expf(s[t][3] - mrow[1]);
            rs[0] += p00 + p01;
            rs[1] += p10 + p11;
            u32 hi, lo;
            split2(p00, p01, hi, lo);
            *(u32*)(Phi + (wid * 16 + g) * ST + t * 8 + pp * 2) = hi;
            *(u32*)(Plo + (wid * 16 + g) * ST + t * 8 + pp * 2) = lo;
            split2(p10, p11, hi, lo);
            *(u32*)(Phi + (wid * 16 + g + 8) * ST + t * 8 + pp * 2) = hi;
            *(u32*)(Plo + (wid * 16 + g + 8) * ST + t * 8 + pp * 2) = lo;
        }
#pragma unroll
        for (int r = 0; r < 2; r++) {
            rs[r] += __shfl_xor_sync(0xffffffffu, rs[r], 1);
            rs[r] += __shfl_xor_sync(0xffffffffu, rs[r], 2);
            lrow[r] = lrow[r] * scl[r] + rs[r];
        }
#pragma unroll
        for (int t = 0; t < 8; t++) {
            o[t][0] *= scl[0]; o[t][1] *= scl[0];
            o[t][2] *= scl[1]; o[t][3] *= scl[1];
        }
        __syncwarp();   // P writes are warp-local (rows wid*16..wid*16+15)

        // ---- GEMM2: O += P V  (V b-frags via ldmatrix.trans on [s][h]) ----
#pragma unroll
        for (int c16 = 0; c16 < 4; c16++) {
            u32 aoff = (u32)(((wid * 16 + lr + lb8 * 8) * ST + c16 * 16 + lb16 * 8) * 2);
            u32 ph[4], pl[4];
            ldsm4(ph[0], ph[1], ph[2], ph[3], sPhi + aoff);
            ldsm4(pl[0], pl[1], pl[2], pl[3], sPlo + aoff);
#pragma unroll
            for (int tp = 0; tp < 4; tp++) {
                u32 voff = (u32)(((c16 * 16 + lr + lb8 * 8) * ST + 16 * tp + lb16 * 8) * 2);
                u32 vh[4], vl[4];
                ldsm4t(vh[0], vh[1], vh[2], vh[3], sVhi + voff);
                ldsm4t(vl[0], vl[1], vl[2], vl[3], sVlo + voff);
                mma16816(o[2 * tp],     ph, vh);
                mma16816(o[2 * tp],     pl, vh);
                mma16816(o[2 * tp],     ph, vl);
                mma16816(o[2 * tp + 1], ph, vh + 2);
                mma16816(o[2 * tp + 1], pl, vh + 2);
                mma16816(o[2 * tp + 1], ph, vl + 2);
            }
        }
    } // kt

    // ---- epilogue ----
    const float inv0 = 1.f / lrow[0], inv1 = 1.f / lrow[1];
    float* Og = out + ((size_t)b * TSEQ + q0) * HS;
#pragma unroll
    for (int t = 0; t < 8; t++) {
        int row = wid * 16 + g, col = t * 8 + pp * 2;
        *(float2*)(Og + (size_t)row * HS + col) =
            make_float2(o[t][0] * inv0, o[t][1] * inv0);
        *(float2*)(Og + (size_t)(row + 8) * HS + col) =
            make_float2(o[t][2] * inv1, o[t][3] * inv1);
    }
}

// =============================================================================
extern "C" void kernel_launch(void* const* d_in, const int* in_sizes, int n_in,
                              void* d_out, int out_size)
{
    const float* xq  = (const float*)d_in[0];
    const float* xkv = (const float*)d_in[1];
    const float* Wq  = (const float*)d_in[2];
    const float* Wk  = (const float*)d_in[3];
    const float* Wv  = (const float*)d_in[4];
    float* out = (float*)d_out;

    cudaFuncSetAttribute(proj_kernel, cudaFuncAttributeMaxDynamicSharedMemorySize, P_SMEM);
    cudaFuncSetAttribute(attn_kernel, cudaFuncAttributeMaxDynamicSharedMemorySize, A_SMEM);

    wsplit_kernel<<<96, 256>>>(Wq, Wk, Wv);
    proj_kernel<<<384, 128, P_SMEM>>>(xq, xkv);
    attn_kernel<<<256, 128, A_SMEM>>>(out);
}